// round 5
// baseline (speedup 1.0000x reference)
#include <cuda_runtime.h>
#include <cstdint>

// dcn_56925496541545: 3x (sparse 9x9 neighbor-mean stencil -> convex combo -> sigmoid),
// output = x[:,0]. Inputs: d_in[0] = x [N,9] f32, d_in[1] = w1 [1] f32. Out: [N] f32.
//
// R4: persistent blocks with a 4-stage cp.async ring buffer (256-patch stages).
//     Each block keeps 3 stages (27.6KB) of loads permanently in flight ->
//     DRAM stream never drains; single wave (grid = SMs*6).

#define THREADS 256
#define PPT 256                       // patches per tile (= per ring stage)
#define STAGES 4
#define STAGE_FLOATS (PPT * 9)        // 2304 floats = 9216 B
#define F4_PER_TILE (STAGE_FLOATS/4)  // 576
#define BLOCKS_PER_SM 6

__device__ __forceinline__ float sigmoid_half_arg(float t_half) {
    // sigmoid(t) = 0.5*tanh(t/2) + 0.5 ; caller passes t/2 (halves folded into weights)
    float th;
    asm("tanh.approx.f32 %0, %1;" : "=f"(th) : "f"(t_half));
    return fmaf(0.5f, th, 0.5f);
}

// 3-iteration patch evaluation with dead-code elimination:
// iter1 keeps all 9, iter2 keeps {0,1,3,4}, iter3 keeps {0}.
__device__ __forceinline__ float patch_eval(const float* __restrict__ a,
                                            float h1, float h3, float h5, float h8) {
    float a0 = a[0], a1 = a[1], a2 = a[2],
          a3 = a[3], a4 = a[4], a5 = a[5],
          a6 = a[6], a7 = a[7], a8 = a[8];

    // ---- iteration 1: all 9 live ----
    {
        const float p14 = a1 + a4, p34 = a3 + a4, p45 = a4 + a5, p47 = a4 + a7;
        const float q02 = a0 + a2, q06 = a0 + a6, q28 = a2 + a8, q68 = a6 + a8;
        const float b00 = p34 + a1;
        const float b02 = p14 + a5;
        const float b20 = p34 + a7;
        const float b22 = p45 + a7;
        const float b01 = (q02 + p34) + a5;
        const float b10 = (q06 + p14) + a7;
        const float b12 = (q28 + p47) + a1;
        const float b21 = (q68 + p45) + a3;
        const float s   = ((b01 + a1) + a7) + q68;   // sum of all 9
        const float b11 = s - a4;

        a0 = sigmoid_half_arg(fmaf(h1, a0, h3 * b00));
        a1 = sigmoid_half_arg(fmaf(h1, a1, h5 * b01));
        a2 = sigmoid_half_arg(fmaf(h1, a2, h3 * b02));
        a3 = sigmoid_half_arg(fmaf(h1, a3, h5 * b10));
        a4 = sigmoid_half_arg(fmaf(h1, a4, h8 * b11));
        a5 = sigmoid_half_arg(fmaf(h1, a5, h5 * b12));
        a6 = sigmoid_half_arg(fmaf(h1, a6, h3 * b20));
        a7 = sigmoid_half_arg(fmaf(h1, a7, h5 * b21));
        a8 = sigmoid_half_arg(fmaf(h1, a8, h3 * b22));
    }

    // ---- iteration 2: only {0,1,3,4} live ----
    float c0, c1, c3, c4;
    {
        const float p34 = a3 + a4;
        const float b00 = p34 + a1;
        const float b01 = ((a0 + a2) + p34) + a5;
        const float b10 = ((a0 + a6) + (a1 + a4)) + a7;
        const float s   = (((b01 + a1) + a7) + a6) + a8;  // sum of all 9
        const float b11 = s - a4;

        c0 = sigmoid_half_arg(fmaf(h1, a0, h3 * b00));
        c1 = sigmoid_half_arg(fmaf(h1, a1, h5 * b01));
        c3 = sigmoid_half_arg(fmaf(h1, a3, h5 * b10));
        c4 = sigmoid_half_arg(fmaf(h1, a4, h8 * b11));
    }

    // ---- iteration 3: only element 0 consumed ----
    const float b00 = (c1 + c3) + c4;
    return sigmoid_half_arg(fmaf(h1, c0, h3 * b00));
}

// Issue one tile's loads into ring stage `stage`. ALWAYS commits a group
// (possibly empty) so the wait_group accounting stays 1-commit-per-slot.
__device__ __forceinline__ void prefetch_tile(const float* __restrict__ x,
                                              long long totalF,
                                              long long tile, long long total_tiles,
                                              uint32_t s_base, int stage, int tid) {
    if (tile < total_tiles) {
        const long long baseF = tile * (long long)STAGE_FLOATS;
        if (baseF + STAGE_FLOATS <= totalF) {   // full tile: 576 float4, 16B-aligned
            const float4* g = reinterpret_cast<const float4*>(x + baseF);
            const uint32_t sb = s_base + (uint32_t)stage * (STAGE_FLOATS * 4u);
            int i = tid;
            asm volatile("cp.async.cg.shared.global [%0], [%1], 16;\n"
                         :: "r"(sb + i * 16u), "l"(g + i));
            i = tid + THREADS;
            asm volatile("cp.async.cg.shared.global [%0], [%1], 16;\n"
                         :: "r"(sb + i * 16u), "l"(g + i));
            if (tid < F4_PER_TILE - 2 * THREADS) {  // 64 threads carry the 3rd float4
                i = tid + 2 * THREADS;
                asm volatile("cp.async.cg.shared.global [%0], [%1], 16;\n"
                             :: "r"(sb + i * 16u), "l"(g + i));
            }
        }
        // partial tile: skip smem staging; compute path reads global directly
    }
    asm volatile("cp.async.commit_group;\n" ::: "memory");
}

__global__ __launch_bounds__(THREADS, BLOCKS_PER_SM)
void dcn_56925496541545_kernel(const float* __restrict__ x,
                               const float* __restrict__ w1p,
                               float* __restrict__ out,
                               int n)  // number of patches
{
    __shared__ float sx[STAGES * STAGE_FLOATS];  // 36864 B

    const int tid = threadIdx.x;
    const long long total_tiles = ((long long)n + PPT - 1) / PPT;
    const long long totalF = (long long)n * 9;
    const uint32_t s_base = (uint32_t)__cvta_generic_to_shared(sx);
    const long long stride = gridDim.x;

    const float w1 = __ldg(w1p);
    const float w2 = 1.0f - w1;
    const float h1 = 0.5f * w1;
    const float h3 = 0.5f * w2 * (1.0f / 3.0f);
    const float h5 = 0.5f * w2 * (1.0f / 5.0f);
    const float h8 = 0.5f * w2 * (1.0f / 8.0f);

    // ---- prologue: fill stages 0..2 ----
    #pragma unroll
    for (int j = 0; j < STAGES - 1; ++j)
        prefetch_tile(x, totalF, blockIdx.x + j * stride, total_tiles, s_base, j, tid);

    // ---- steady state: issue k+3, wait k, compute k ----
    long long k = 0;
    for (long long t = blockIdx.x; t < total_tiles; t += stride, ++k) {
        prefetch_tile(x, totalF, blockIdx.x + (k + 3) * stride, total_tiles,
                      s_base, (int)((k + 3) & (STAGES - 1)), tid);

        asm volatile("cp.async.wait_group %0;\n" :: "n"(STAGES - 1) : "memory");
        __syncthreads();

        const int stage = (int)(k & (STAGES - 1));
        const long long p = t * PPT + tid;
        const long long baseF = t * (long long)STAGE_FLOATS;
        if (baseF + STAGE_FLOATS <= totalF) {
            // full tile: data staged in shared (stride-9 reads: conflict-free)
            out[p] = patch_eval(&sx[stage * STAGE_FLOATS + tid * 9], h1, h3, h5, h8);
        } else if (p < (long long)n) {
            // partial tail tile: read global directly
            out[p] = patch_eval(x + p * 9, h1, h3, h5, h8);
        }

        __syncthreads();   // protect stage before it is re-filled next iteration
    }
}

extern "C" void kernel_launch(void* const* d_in, const int* in_sizes, int n_in,
                              void* d_out, int out_size) {
    const float* x   = (const float*)d_in[0];
    const float* w1  = (const float*)d_in[1];
    float* out       = (float*)d_out;
    const int n      = in_sizes[0] / 9;  // number of patches

    int sms = 148;
    cudaDeviceGetAttribute(&sms, cudaDevAttrMultiProcessorCount, 0);

    long long total_tiles = ((long long)n + PPT - 1) / PPT;
    long long blocks = (long long)sms * BLOCKS_PER_SM;
    if (blocks > total_tiles) blocks = total_tiles;

    dcn_56925496541545_kernel<<<(int)blocks, THREADS>>>(x, w1, out, n);
}

// round 6
// speedup vs baseline: 1.0597x; 1.0597x over previous
#include <cuda_runtime.h>
#include <cstdint>

// dcn_56925496541545: 3x (sparse 9x9 neighbor-mean stencil -> convex combo -> sigmoid),
// output = x[:,0]. Inputs: d_in[0] = x [N,9] f32, d_in[1] = w1 [1] f32. Out: [N] f32.
//
// R5: warp-autonomous persistent pipelines. Each warp grid-strides over
//     32-patch tiles with a private 4-stage cp.async ring (1152 B/stage).
//     No __syncthreads in the loop -- only wait_group + __syncwarp. Every
//     warp keeps 3 groups permanently in flight; DRAM stream never drains.

#define THREADS 256
#define WPB 8                    // warps per block
#define STAGES 4
#define TILE_P 32                // patches per warp-tile
#define TILE_F4 72               // float4s per tile (32*9/4)
#define STAGE_BYTES 1152         // 288 floats
#define BLOCKS_PER_SM 6

__device__ __forceinline__ float sigmoid_half_arg(float t_half) {
    // sigmoid(t) = 0.5*tanh(t/2) + 0.5 ; caller passes t/2 (halves folded into weights)
    float th;
    asm("tanh.approx.f32 %0, %1;" : "=f"(th) : "f"(t_half));
    return fmaf(0.5f, th, 0.5f);
}

// 3-iteration patch evaluation with dead-code elimination:
// iter1 keeps all 9, iter2 keeps {0,1,3,4}, iter3 keeps {0}.
__device__ __forceinline__ float patch_eval(const float* __restrict__ a,
                                            float h1, float h3, float h5, float h8) {
    float a0 = a[0], a1 = a[1], a2 = a[2],
          a3 = a[3], a4 = a[4], a5 = a[5],
          a6 = a[6], a7 = a[7], a8 = a[8];

    // ---- iteration 1: all 9 live ----
    {
        const float p14 = a1 + a4, p34 = a3 + a4, p45 = a4 + a5, p47 = a4 + a7;
        const float q02 = a0 + a2, q06 = a0 + a6, q28 = a2 + a8, q68 = a6 + a8;
        const float b00 = p34 + a1;
        const float b02 = p14 + a5;
        const float b20 = p34 + a7;
        const float b22 = p45 + a7;
        const float b01 = (q02 + p34) + a5;
        const float b10 = (q06 + p14) + a7;
        const float b12 = (q28 + p47) + a1;
        const float b21 = (q68 + p45) + a3;
        const float s   = ((b01 + a1) + a7) + q68;   // sum of all 9
        const float b11 = s - a4;

        a0 = sigmoid_half_arg(fmaf(h1, a0, h3 * b00));
        a1 = sigmoid_half_arg(fmaf(h1, a1, h5 * b01));
        a2 = sigmoid_half_arg(fmaf(h1, a2, h3 * b02));
        a3 = sigmoid_half_arg(fmaf(h1, a3, h5 * b10));
        a4 = sigmoid_half_arg(fmaf(h1, a4, h8 * b11));
        a5 = sigmoid_half_arg(fmaf(h1, a5, h5 * b12));
        a6 = sigmoid_half_arg(fmaf(h1, a6, h3 * b20));
        a7 = sigmoid_half_arg(fmaf(h1, a7, h5 * b21));
        a8 = sigmoid_half_arg(fmaf(h1, a8, h3 * b22));
    }

    // ---- iteration 2: only {0,1,3,4} live ----
    float c0, c1, c3, c4;
    {
        const float p34 = a3 + a4;
        const float b00 = p34 + a1;
        const float b01 = ((a0 + a2) + p34) + a5;
        const float b10 = ((a0 + a6) + (a1 + a4)) + a7;
        const float s   = (((b01 + a1) + a7) + a6) + a8;  // sum of all 9
        const float b11 = s - a4;

        c0 = sigmoid_half_arg(fmaf(h1, a0, h3 * b00));
        c1 = sigmoid_half_arg(fmaf(h1, a1, h5 * b01));
        c3 = sigmoid_half_arg(fmaf(h1, a3, h5 * b10));
        c4 = sigmoid_half_arg(fmaf(h1, a4, h8 * b11));
    }

    // ---- iteration 3: only element 0 consumed ----
    const float b00 = (c1 + c3) + c4;
    return sigmoid_half_arg(fmaf(h1, c0, h3 * b00));
}

// Issue one 32-patch tile's loads into this warp's ring stage. Always commits
// (possibly empty group) so wait_group accounting stays 1-commit-per-slot.
__device__ __forceinline__ void prefetch_tile_w(const float4* __restrict__ x4,
                                                int tile, int total_tiles,
                                                uint32_t warp_sbase, int stage, int lane) {
    if (tile < total_tiles) {
        const float4* g = x4 + (uint32_t)tile * TILE_F4;   // 1152B-aligned
        const uint32_t sb = warp_sbase + (uint32_t)stage * STAGE_BYTES;
        asm volatile("cp.async.cg.shared.global [%0], [%1], 16;\n"
                     :: "r"(sb + lane * 16u), "l"(g + lane));
        asm volatile("cp.async.cg.shared.global [%0], [%1], 16;\n"
                     :: "r"(sb + (lane + 32) * 16u), "l"(g + lane + 32));
        if (lane < TILE_F4 - 64) {   // 8 lanes carry the 3rd float4
            asm volatile("cp.async.cg.shared.global [%0], [%1], 16;\n"
                         :: "r"(sb + (lane + 64) * 16u), "l"(g + lane + 64));
        }
    }
    asm volatile("cp.async.commit_group;\n" ::: "memory");
}

__global__ __launch_bounds__(THREADS, BLOCKS_PER_SM)
void dcn_56925496541545_kernel(const float* __restrict__ x,
                               const float* __restrict__ w1p,
                               float* __restrict__ out,
                               int n)  // number of patches
{
    __shared__ float sx[WPB * STAGES * (STAGE_BYTES / 4)];  // 36864 B

    const int lane = threadIdx.x & 31;
    const int wp   = threadIdx.x >> 5;
    const int W    = gridDim.x * WPB;               // total warps in grid
    const int gw   = blockIdx.x * WPB + wp;         // this warp's global id
    const int total_tiles = n >> 5;                 // full 32-patch tiles

    const uint32_t warp_sbase =
        (uint32_t)__cvta_generic_to_shared(sx) + (uint32_t)wp * (STAGES * STAGE_BYTES);
    const float4* x4 = reinterpret_cast<const float4*>(x);

    const float w1 = __ldg(w1p);
    const float w2 = 1.0f - w1;
    const float h1 = 0.5f * w1;
    const float h3 = 0.5f * w2 * (1.0f / 3.0f);
    const float h5 = 0.5f * w2 * (1.0f / 5.0f);
    const float h8 = 0.5f * w2 * (1.0f / 8.0f);

    // ---- prologue: fill stages 0..2 (3 groups permanently in flight) ----
    prefetch_tile_w(x4, gw,         total_tiles, warp_sbase, 0, lane);
    prefetch_tile_w(x4, gw + W,     total_tiles, warp_sbase, 1, lane);
    prefetch_tile_w(x4, gw + 2 * W, total_tiles, warp_sbase, 2, lane);

    // ---- steady state: wait k, publish, issue k+3, compute k ----
    int k = 0;
    for (int t = gw; t < total_tiles; t += W, ++k) {
        asm volatile("cp.async.wait_group %0;\n" :: "n"(STAGES - 2) : "memory");
        __syncwarp();   // publish stage k to all lanes; also fences compute k-1
                        // before stage (k+3)&3 == (k-1)&3 is overwritten below

        prefetch_tile_w(x4, t + 3 * W, total_tiles, warp_sbase, (k + 3) & (STAGES - 1), lane);

        const float* a = reinterpret_cast<const float*>(
            reinterpret_cast<const char*>(sx)
            + (wp * STAGES + (k & (STAGES - 1))) * STAGE_BYTES) + lane * 9;
        out[t * TILE_P + lane] = patch_eval(a, h1, h3, h5, h8);  // 128B coalesced store
    }

    // ---- remainder patches (n % 32): one warp, direct global reads ----
    if (gw == 0 && (n & 31)) {
        const int p = (total_tiles << 5) + lane;
        if (p < n)
            out[p] = patch_eval(x + p * 9, h1, h3, h5, h8);
    }
}

extern "C" void kernel_launch(void* const* d_in, const int* in_sizes, int n_in,
                              void* d_out, int out_size) {
    const float* x   = (const float*)d_in[0];
    const float* w1  = (const float*)d_in[1];
    float* out       = (float*)d_out;
    const int n      = in_sizes[0] / 9;  // number of patches

    int sms = 148;
    cudaDeviceGetAttribute(&sms, cudaDevAttrMultiProcessorCount, 0);

    long long want = (long long)sms * BLOCKS_PER_SM;
    long long tiles_cap = ((long long)(n >> 5) + WPB - 1) / WPB;  // ≥1 tile per warp
    long long blocks = want < tiles_cap ? want : tiles_cap;
    if (blocks < 1) blocks = 1;

    dcn_56925496541545_kernel<<<(int)blocks, THREADS>>>(x, w1, out, n);
}